// round 10
// baseline (speedup 1.0000x reference)
#include <cuda_runtime.h>
#include <cuda_bf16.h>
#include <cstdint>

// Problem constants (fixed shapes per reference)
#define NN_MAX 50000
#define EE_MAX 800000

// ---------------- scratch (device globals; no runtime allocation) ----------------
__device__ __align__(16) float g_Q1[NN_MAX * 128];
__device__ __align__(16) float g_K1[NN_MAX * 128];
__device__ __align__(16) float g_V1[NN_MAX * 128];
__device__ __align__(16) float g_S1[NN_MAX * 128];
__device__ __align__(16) float g_h [NN_MAX * 128];
__device__ __align__(16) float g_Q2[NN_MAX * 64];
__device__ __align__(16) float g_K2[NN_MAX * 64];
__device__ __align__(16) float g_V2[NN_MAX * 64];
__device__ __align__(16) float g_S2[NN_MAX * 64];

__device__ int g_cnt[NN_MAX];
__device__ int g_rowptr[NN_MAX + 1];
__device__ int g_cur[NN_MAX];
__device__ int g_psrc[EE_MAX];

// Pre-split tf32 planes: (hi,lo) uint2 per element
__device__ __align__(16) uint2 g_A1[NN_MAX * 128];     // split(x)
__device__ __align__(16) uint2 g_A2[NN_MAX * 128];     // split(g_h)
__device__ __align__(16) uint2 g_Wt1[128 * 512];       // [k][z*128+col]
__device__ __align__(16) uint2 g_Wt2[128 * 256];       // [k][z*64+col]

// ---------------- CSR build ----------------
__global__ void k_zero(int n) {
    int i = blockIdx.x * blockDim.x + threadIdx.x;
    if (i < n) g_cnt[i] = 0;
}

__global__ void k_hist(const int* __restrict__ dst, int e) {
    int i = blockIdx.x * blockDim.x + threadIdx.x;
    if (i < e) atomicAdd(&g_cnt[dst[i]], 1);
}

__global__ __launch_bounds__(1024) void k_scan(int n) {
    int tid = threadIdx.x;
    int CH = (n + 1023) >> 10;
    int base = tid * CH;
    int lim = min(base + CH, n);

    int sum = 0;
    for (int i = base; i < lim; i++) sum += g_cnt[i];

    int lane = tid & 31, wid = tid >> 5;
    int v = sum;
    #pragma unroll
    for (int off = 1; off < 32; off <<= 1) {
        int t = __shfl_up_sync(0xffffffffu, v, off);
        if (lane >= off) v += t;
    }
    __shared__ int wsum[32];
    if (lane == 31) wsum[wid] = v;
    __syncthreads();
    if (wid == 0) {
        int w = wsum[lane];
        #pragma unroll
        for (int off = 1; off < 32; off <<= 1) {
            int t = __shfl_up_sync(0xffffffffu, w, off);
            if (lane >= off) w += t;
        }
        wsum[lane] = w;
    }
    __syncthreads();
    int excl = v - sum + (wid ? wsum[wid - 1] : 0);

    int run = excl;
    for (int i = base; i < lim; i++) {
        int c = g_cnt[i];
        g_rowptr[i] = run;
        g_cur[i] = run;
        run += c;
    }
    if (tid == 1023) g_rowptr[n] = run;
}

__global__ void k_scatter(const int* __restrict__ src, const int* __restrict__ dst, int e) {
    int i = blockIdx.x * blockDim.x + threadIdx.x;
    if (i < e) {
        int d = dst[i];
        int pos = atomicAdd(&g_cur[d], 1);
        g_psrc[pos] = src[i];
    }
}

// ---------------- tf32 split prep ----------------
__device__ __forceinline__ unsigned f2tf(float x) {
    unsigned r;
    asm("cvt.rna.tf32.f32 %0, %1;" : "=r"(r) : "f"(x));
    return r;
}

__device__ __forceinline__ uint2 split_tf32(float x) {
    unsigned hi = f2tf(x);
    float lof = x - __uint_as_float(hi);
    unsigned lo = f2tf(lof);
    return make_uint2(hi, lo);
}

// which=0: src=x -> g_A1; which=1: src=g_h -> g_A2
__global__ void k_splitA(const float* __restrict__ srcIn, int total, int which) {
    const float* src = srcIn ? srcIn : g_h;
    uint2* dst = which ? g_A2 : g_A1;
    int i = blockIdx.x * blockDim.x + threadIdx.x;
    if (i < total) dst[i] = split_tf32(src[i]);
}

// gW[k][z*NOUT+col] = split(W_z[k][col])
__global__ void k_splitW(const float* __restrict__ W0, const float* __restrict__ W1,
                         const float* __restrict__ W2, const float* __restrict__ W3,
                         int NOUT, int which)
{
    uint2* dst = which ? g_Wt2 : g_Wt1;
    int total = 4 * 128 * NOUT;
    int idx = blockIdx.x * blockDim.x + threadIdx.x;
    if (idx >= total) return;
    int z = idx / (128 * NOUT);
    int r = idx - z * (128 * NOUT);
    int k = r / NOUT;
    int col = r - k * NOUT;
    const float* W = (z == 0) ? W0 : (z == 1) ? W1 : (z == 2) ? W2 : W3;
    dst[(size_t)k * (4 * NOUT) + z * NOUT + col] = split_tf32(W[(size_t)k * NOUT + col]);
}

// ---------------- fused tf32-3x GEMM: one CTA per 128-row strip, all 4 outputs ----------------
__device__ __forceinline__ float* sel_out(int s) {
    switch (s) {
        case 0: return g_Q1; case 1: return g_K1; case 2: return g_V1; case 3: return g_S1;
        case 4: return g_Q2; case 5: return g_K2; case 6: return g_V2; default: return g_S2;
    }
}

__device__ __forceinline__ void mma1688(float& c0, float& c1, float& c2, float& c3,
                                        unsigned a0, unsigned a1, unsigned a2, unsigned a3,
                                        unsigned b0, unsigned b1) {
    asm volatile("mma.sync.aligned.m16n8k8.row.col.f32.tf32.tf32.f32 "
                 "{%0,%1,%2,%3}, {%4,%5,%6,%7}, {%8,%9}, {%0,%1,%2,%3};"
                 : "+f"(c0), "+f"(c1), "+f"(c2), "+f"(c3)
                 : "r"(a0), "r"(a1), "r"(a2), "r"(a3), "r"(b0), "r"(b1));
}

#define A_STRIDE 132   // uint2 units per A row (128 + 4 pad) -> 132%16==4, conflict-free frags
#define B_STRIDE 68    // uint2 units per B k-row (64 + 4 pad) -> 68%16==4
#define B_BUF    1088  // 16 * 68

template<int NOUT>
__global__ __launch_bounds__(256) void gemm_tc2(const float* __restrict__ b0p, const float* __restrict__ b1p,
                                                const float* __restrict__ b2p, const float* __restrict__ b3p,
                                                int M, int outBase)
{
    constexpr int NCT = (NOUT == 128) ? 8 : 4;       // 64-wide column tiles
    constexpr int COLSALL = 4 * NOUT;                // 512 or 256
    const uint2* __restrict__ gA = (NOUT == 128) ? g_A1 : g_A2;
    const uint2* __restrict__ gW = (NOUT == 128) ? g_Wt1 : g_Wt2;

    extern __shared__ char smem[];
    uint2* As = (uint2*)smem;                        // [row][k], stride A_STRIDE
    uint2* Bs = (uint2*)(smem + 128 * A_STRIDE * 8); // 2 bufs [k][col], stride B_STRIDE

    int tid = threadIdx.x;
    int lane = tid & 31;
    int w = tid >> 5;
    int rowW = (w & 3) * 32;
    int colW = (w >> 2) * 32;
    int g = lane >> 2, t = lane & 3;
    int rowBase = blockIdx.x * 128;

    // ---- A fill: full 128x128 (hi,lo) uint2 = 128 rows x 64 uint4, once per block ----
    for (int it = tid; it < 8192; it += 256) {       // FIX: 8192 uint4 items (was 4096)
        int row = it >> 6;                           // 0..127
        int c2 = (it & 63) * 2;                      // uint2 col 0..126
        int gr = rowBase + row;
        uint4 v = make_uint4(0u, 0u, 0u, 0u);
        if (gr < M) v = *(const uint4*)(gA + (size_t)gr * 128 + c2);
        *(uint4*)&As[row * A_STRIDE + c2] = v;
    }

    for (int ct = 0; ct < NCT; ct++) {
        __syncthreads();   // A visible (ct=0) / prev-ct B reads done
        // fill B(ct, kk=0) into buf 0
        for (int it = tid; it < 512; it += 256) {
            int k = it >> 5;
            int c2 = (it & 31) * 2;
            *(uint4*)&Bs[k * B_STRIDE + c2] =
                *(const uint4*)(gW + (size_t)k * COLSALL + ct * 64 + c2);
        }
        __syncthreads();

        float acc[2][4][4];
        #pragma unroll
        for (int mi = 0; mi < 2; mi++)
            #pragma unroll
            for (int ni = 0; ni < 4; ni++)
                #pragma unroll
                for (int r = 0; r < 4; r++) acc[mi][ni][r] = 0.f;

        #pragma unroll
        for (int kk = 0; kk < 8; kk++) {
            int cur = kk & 1;
            if (kk < 7) {  // prefetch next B tile into alternate buffer
                int kn = kk + 1;
                for (int it = tid; it < 512; it += 256) {
                    int k = it >> 5;
                    int c2 = (it & 31) * 2;
                    *(uint4*)&Bs[(cur ^ 1) * B_BUF + k * B_STRIDE + c2] =
                        *(const uint4*)(gW + (size_t)(kn * 16 + k) * COLSALL + ct * 64 + c2);
                }
            }
            #pragma unroll
            for (int ks = 0; ks < 2; ks++) {
                int kA = kk * 16 + ks * 8;
                uint2 af[2][4];
                #pragma unroll
                for (int mi = 0; mi < 2; mi++) {
                    int r0 = rowW + mi * 16 + g;
                    af[mi][0] = As[(r0    ) * A_STRIDE + kA + t];
                    af[mi][1] = As[(r0 + 8) * A_STRIDE + kA + t];
                    af[mi][2] = As[(r0    ) * A_STRIDE + kA + t + 4];
                    af[mi][3] = As[(r0 + 8) * A_STRIDE + kA + t + 4];
                }
                uint2 bf[4][2];
                #pragma unroll
                for (int ni = 0; ni < 4; ni++) {
                    int col = colW + ni * 8 + g;
                    bf[ni][0] = Bs[cur * B_BUF + (ks * 8 + t    ) * B_STRIDE + col];
                    bf[ni][1] = Bs[cur * B_BUF + (ks * 8 + t + 4) * B_STRIDE + col];
                }
                #pragma unroll
                for (int mi = 0; mi < 2; mi++) {
                    #pragma unroll
                    for (int ni = 0; ni < 4; ni++) {
                        float* c = acc[mi][ni];
                        mma1688(c[0], c[1], c[2], c[3],
                                af[mi][0].x, af[mi][1].x, af[mi][2].x, af[mi][3].x,
                                bf[ni][0].x, bf[ni][1].x);
                        mma1688(c[0], c[1], c[2], c[3],
                                af[mi][0].x, af[mi][1].x, af[mi][2].x, af[mi][3].x,
                                bf[ni][0].y, bf[ni][1].y);
                        mma1688(c[0], c[1], c[2], c[3],
                                af[mi][0].y, af[mi][1].y, af[mi][2].y, af[mi][3].y,
                                bf[ni][0].x, bf[ni][1].x);
                    }
                }
            }
            __syncthreads();
        }

        // ---- epilogue for this column tile ----
        int z, colBase;
        if (NOUT == 128) { z = ct >> 1; colBase = (ct & 1) * 64; }
        else             { z = ct;      colBase = 0; }
        const float* bias = (z == 0) ? b0p : (z == 1) ? b1p : (z == 2) ? b2p : b3p;
        float* C = sel_out(outBase + z);

        #pragma unroll
        for (int ni = 0; ni < 4; ni++) {
            int col = colBase + colW + ni * 8 + 2 * t;
            float bx = bias[col], by = bias[col + 1];
            #pragma unroll
            for (int mi = 0; mi < 2; mi++) {
                int r0 = rowBase + rowW + mi * 16 + g;
                float* c = acc[mi][ni];
                if (r0 < M) {
                    float2 o = make_float2(c[0] + bx, c[1] + by);
                    *(float2*)(C + (size_t)r0 * NOUT + col) = o;
                }
                if (r0 + 8 < M) {
                    float2 o = make_float2(c[2] + bx, c[3] + by);
                    *(float2*)(C + (size_t)(r0 + 8) * NOUT + col) = o;
                }
            }
        }
    }
}

// ---------------- layer-1 aggregation: warp per node, online softmax, H=8 D=16 ----------------
// 2-deep software pipeline: K/V gathers for edge e+2 issued while computing edge e.
__global__ __launch_bounds__(256) void agg1_kernel(int Nn)
{
    int warp = (blockIdx.x * blockDim.x + threadIdx.x) >> 5;
    int lane = threadIdx.x & 31;
    if (warp >= Nn) return;
    int n = warp;

    const float4* Q4 = (const float4*)g_Q1;
    const float4* K4 = (const float4*)g_K1;
    const float4* V4 = (const float4*)g_V1;
    const float4* S4 = (const float4*)g_S1;

    float4 q = Q4[(size_t)n * 32 + lane];

    int beg = g_rowptr[n];
    int end = g_rowptr[n + 1];

    float m = -1e30f, s = 0.f;
    float4 acc = make_float4(0.f, 0.f, 0.f, 0.f);

    if (beg < end) {
        int s0 = g_psrc[beg];
        float4 kA = K4[(size_t)s0 * 32 + lane];
        float4 vA = V4[(size_t)s0 * 32 + lane];
        float4 kB = kA, vB = vA;
        if (beg + 1 < end) {
            int s1 = g_psrc[beg + 1];
            kB = K4[(size_t)s1 * 32 + lane];
            vB = V4[(size_t)s1 * 32 + lane];
        }
        for (int e = beg; e < end; e++) {
            float4 kC = kA, vC = vA;
            if (e + 2 < end) {
                int s2 = g_psrc[e + 2];
                kC = K4[(size_t)s2 * 32 + lane];
                vC = V4[(size_t)s2 * 32 + lane];
            }

            float d = kA.x * q.x + kA.y * q.y + kA.z * q.z + kA.w * q.w;
            d += __shfl_xor_sync(0xffffffffu, d, 1);
            d += __shfl_xor_sync(0xffffffffu, d, 2);
            float sc = d * 0.25f;

            float mn = fmaxf(m, sc);
            float c  = __expf(m - mn);
            float p  = __expf(sc - mn);
            s = s * c + p;
            acc.x = acc.x * c + p * vA.x;
            acc.y = acc.y * c + p * vA.y;
            acc.z = acc.z * c + p * vA.z;
            acc.w = acc.w * c + p * vA.w;
            m = mn;

            kA = kB; vA = vB; kB = kC; vB = vC;
        }
    }

    float inv = 1.f / (s + 1e-16f);
    float4 sk = S4[(size_t)n * 32 + lane];
    float4 o;
    o.x = fmaxf(acc.x * inv + sk.x, 0.f);
    o.y = fmaxf(acc.y * inv + sk.y, 0.f);
    o.z = fmaxf(acc.z * inv + sk.z, 0.f);
    o.w = fmaxf(acc.w * inv + sk.w, 0.f);
    ((float4*)g_h)[(size_t)n * 32 + lane] = o;
}

// ---------------- layer-2 aggregation: warp per node, online softmax, H=1 D=64 ----------------
__global__ __launch_bounds__(256) void agg2_kernel(float* __restrict__ out, int Nn)
{
    int warp = (blockIdx.x * blockDim.x + threadIdx.x) >> 5;
    int lane = threadIdx.x & 31;
    if (warp >= Nn) return;
    int n = warp;

    const float2* Q2 = (const float2*)g_Q2;
    const float2* K2 = (const float2*)g_K2;
    const float2* V2 = (const float2*)g_V2;
    const float2* S2 = (const float2*)g_S2;

    float2 q = Q2[(size_t)n * 32 + lane];

    int beg = g_rowptr[n];
    int end = g_rowptr[n + 1];

    float m = -1e30f, s = 0.f;
    float2 acc = make_float2(0.f, 0.f);

    if (beg < end) {
        int s0 = g_psrc[beg];
        float2 kA = K2[(size_t)s0 * 32 + lane];
        float2 vA = V2[(size_t)s0 * 32 + lane];
        float2 kB = kA, vB = vA;
        if (beg + 1 < end) {
            int s1 = g_psrc[beg + 1];
            kB = K2[(size_t)s1 * 32 + lane];
            vB = V2[(size_t)s1 * 32 + lane];
        }
        for (int e = beg; e < end; e++) {
            float2 kC = kA, vC = vA;
            if (e + 2 < end) {
                int s2 = g_psrc[e + 2];
                kC = K2[(size_t)s2 * 32 + lane];
                vC = V2[(size_t)s2 * 32 + lane];
            }

            float d = kA.x * q.x + kA.y * q.y;
            #pragma unroll
            for (int off = 16; off > 0; off >>= 1)
                d += __shfl_xor_sync(0xffffffffu, d, off);
            float sc = d * 0.125f;

            float mn = fmaxf(m, sc);
            float c  = __expf(m - mn);
            float p  = __expf(sc - mn);
            s = s * c + p;
            acc.x = acc.x * c + p * vA.x;
            acc.y = acc.y * c + p * vA.y;
            m = mn;

            kA = kB; vA = vB; kB = kC; vB = vC;
        }
    }

    float inv = 1.f / (s + 1e-16f);
    float2 sk = S2[(size_t)n * 32 + lane];
    float2 o;
    o.x = acc.x * inv + sk.x;
    o.y = acc.y * inv + sk.y;
    ((float2*)out)[(size_t)n * 32 + lane] = o;
}

// ---------------- launch ----------------
extern "C" void kernel_launch(void* const* d_in, const int* in_sizes, int n_in,
                              void* d_out, int out_size)
{
    const float* x   = (const float*)d_in[0];
    const float* Wq1 = (const float*)d_in[1];  const float* bq1 = (const float*)d_in[2];
    const float* Wk1 = (const float*)d_in[3];  const float* bk1 = (const float*)d_in[4];
    const float* Wv1 = (const float*)d_in[5];  const float* bv1 = (const float*)d_in[6];
    const float* Ws1 = (const float*)d_in[7];  const float* bs1 = (const float*)d_in[8];
    const float* Wq2 = (const float*)d_in[9];  const float* bq2 = (const float*)d_in[10];
    const float* Wk2 = (const float*)d_in[11]; const float* bk2 = (const float*)d_in[12];
    const float* Wv2 = (const float*)d_in[13]; const float* bv2 = (const float*)d_in[14];
    const float* Ws2 = (const float*)d_in[15]; const float* bs2 = (const float*)d_in[16];
    const int* esrc  = (const int*)d_in[17];
    const int* edst  = (const int*)d_in[18];
    float* out = (float*)d_out;

    int Nn = in_sizes[0] / 128;
    int E  = in_sizes[17];

    constexpr int SMEM = 128 * A_STRIDE * 8 + 2 * B_BUF * 8;  // 135168 + 17408 = 152576
    cudaFuncSetAttribute(gemm_tc2<128>, cudaFuncAttributeMaxDynamicSharedMemorySize, SMEM);
    cudaFuncSetAttribute(gemm_tc2<64>,  cudaFuncAttributeMaxDynamicSharedMemorySize, SMEM);

    // CSR build
    k_zero<<<(Nn + 255) / 256, 256>>>(Nn);
    k_hist<<<(E + 255) / 256, 256>>>(edst, E);
    k_scan<<<1, 1024>>>(Nn);
    k_scatter<<<(E + 255) / 256, 256>>>(esrc, edst, E);

    // tf32 split prep
    int totA = Nn * 128;
    k_splitA<<<(totA + 255) / 256, 256>>>(x, totA, 0);
    k_splitW<<<(4 * 128 * 128 + 255) / 256, 256>>>(Wq1, Wk1, Wv1, Ws1, 128, 0);
    k_splitW<<<(4 * 128 * 64 + 255) / 256, 256>>>(Wq2, Wk2, Wv2, Ws2, 64, 1);

    int rowBlocks = (Nn + 127) / 128;

    // layer-1 projections (fused 4-output, tf32 3x)
    gemm_tc2<128><<<rowBlocks, 256, SMEM>>>(bq1, bk1, bv1, bs1, Nn, 0);

    int aggBlocks = (Nn + 7) / 8;
    agg1_kernel<<<aggBlocks, 256>>>(Nn);

    // split hidden for layer-2 A
    k_splitA<<<(totA + 255) / 256, 256>>>(nullptr, totA, 1);

    // layer-2 projections
    gemm_tc2<64><<<rowBlocks, 256, SMEM>>>(bq2, bk2, bv2, bs2, Nn, 4);

    agg2_kernel<<<aggBlocks, 256>>>(out, Nn);
}

// round 11
// speedup vs baseline: 1.2702x; 1.2702x over previous
#include <cuda_runtime.h>
#include <cuda_bf16.h>
#include <cstdint>

// Problem constants (fixed shapes per reference)
#define NN_MAX 50000
#define EE_MAX 800000

// ---------------- scratch (device globals; no runtime allocation) ----------------
__device__ __align__(16) float g_Q1[NN_MAX * 128];
__device__ __align__(16) float g_K1[NN_MAX * 128];
__device__ __align__(16) float g_V1[NN_MAX * 128];
__device__ __align__(16) float g_S1[NN_MAX * 128];
__device__ __align__(16) float g_h [NN_MAX * 128];
__device__ __align__(16) float g_Q2[NN_MAX * 64];
__device__ __align__(16) float g_K2[NN_MAX * 64];
__device__ __align__(16) float g_V2[NN_MAX * 64];
__device__ __align__(16) float g_S2[NN_MAX * 64];

__device__ int g_cnt[NN_MAX];
__device__ int g_rowptr[NN_MAX + 1];
__device__ int g_cur[NN_MAX];
__device__ int g_psrc[EE_MAX];

// Pre-split tf32 planes: (hi,lo) uint2 per element
__device__ __align__(16) uint2 g_A1[NN_MAX * 128];     // split(x)
__device__ __align__(16) uint2 g_A2[NN_MAX * 128];     // split(g_h)
__device__ __align__(16) uint2 g_Wt1[128 * 512];       // [k][z*128+col]
__device__ __align__(16) uint2 g_Wt2[128 * 256];       // [k][z*64+col]

// ---------------- CSR build ----------------
__global__ void k_zero(int n) {
    int i = blockIdx.x * blockDim.x + threadIdx.x;
    if (i < n) g_cnt[i] = 0;
}

__global__ void k_hist(const int* __restrict__ dst, int e) {
    int i = blockIdx.x * blockDim.x + threadIdx.x;
    if (i < e) atomicAdd(&g_cnt[dst[i]], 1);
}

__global__ __launch_bounds__(1024) void k_scan(int n) {
    int tid = threadIdx.x;
    int CH = (n + 1023) >> 10;
    int base = tid * CH;
    int lim = min(base + CH, n);

    int sum = 0;
    for (int i = base; i < lim; i++) sum += g_cnt[i];

    int lane = tid & 31, wid = tid >> 5;
    int v = sum;
    #pragma unroll
    for (int off = 1; off < 32; off <<= 1) {
        int t = __shfl_up_sync(0xffffffffu, v, off);
        if (lane >= off) v += t;
    }
    __shared__ int wsum[32];
    if (lane == 31) wsum[wid] = v;
    __syncthreads();
    if (wid == 0) {
        int w = wsum[lane];
        #pragma unroll
        for (int off = 1; off < 32; off <<= 1) {
            int t = __shfl_up_sync(0xffffffffu, w, off);
            if (lane >= off) w += t;
        }
        wsum[lane] = w;
    }
    __syncthreads();
    int excl = v - sum + (wid ? wsum[wid - 1] : 0);

    int run = excl;
    for (int i = base; i < lim; i++) {
        int c = g_cnt[i];
        g_rowptr[i] = run;
        g_cur[i] = run;
        run += c;
    }
    if (tid == 1023) g_rowptr[n] = run;
}

__global__ void k_scatter(const int* __restrict__ src, const int* __restrict__ dst, int e) {
    int i = blockIdx.x * blockDim.x + threadIdx.x;
    if (i < e) {
        int d = dst[i];
        int pos = atomicAdd(&g_cur[d], 1);
        g_psrc[pos] = src[i];
    }
}

// ---------------- tf32 split prep ----------------
__device__ __forceinline__ unsigned f2tf(float x) {
    unsigned r;
    asm("cvt.rna.tf32.f32 %0, %1;" : "=r"(r) : "f"(x));
    return r;
}

__device__ __forceinline__ uint2 split_tf32(float x) {
    unsigned hi = f2tf(x);
    float lof = x - __uint_as_float(hi);
    unsigned lo = f2tf(lof);
    return make_uint2(hi, lo);
}

// which=0: src=x -> g_A1; which=1: src=g_h -> g_A2
__global__ void k_splitA(const float* __restrict__ srcIn, int total, int which) {
    const float* src = srcIn ? srcIn : g_h;
    uint2* dst = which ? g_A2 : g_A1;
    int i = blockIdx.x * blockDim.x + threadIdx.x;
    if (i < total) dst[i] = split_tf32(src[i]);
}

// gW[k][z*NOUT+col] = split(W_z[k][col])
__global__ void k_splitW(const float* __restrict__ W0, const float* __restrict__ W1,
                         const float* __restrict__ W2, const float* __restrict__ W3,
                         int NOUT, int which)
{
    uint2* dst = which ? g_Wt2 : g_Wt1;
    int total = 4 * 128 * NOUT;
    int idx = blockIdx.x * blockDim.x + threadIdx.x;
    if (idx >= total) return;
    int z = idx / (128 * NOUT);
    int r = idx - z * (128 * NOUT);
    int k = r / NOUT;
    int col = r - k * NOUT;
    const float* W = (z == 0) ? W0 : (z == 1) ? W1 : (z == 2) ? W2 : W3;
    dst[(size_t)k * (4 * NOUT) + z * NOUT + col] = split_tf32(W[(size_t)k * NOUT + col]);
}

// ---------------- tf32-3x GEMM, R3 structure + pre-split planes ----------------
// Tile: BM=128, BN=64, BK=16. 256 threads = 8 warps (4 row x 2 col), warp tile 32x32.
__device__ __forceinline__ float* sel_out(int s) {
    switch (s) {
        case 0: return g_Q1; case 1: return g_K1; case 2: return g_V1; case 3: return g_S1;
        case 4: return g_Q2; case 5: return g_K2; case 6: return g_V2; default: return g_S2;
    }
}

__device__ __forceinline__ void mma1688(float& c0, float& c1, float& c2, float& c3,
                                        unsigned a0, unsigned a1, unsigned a2, unsigned a3,
                                        unsigned b0, unsigned b1) {
    asm volatile("mma.sync.aligned.m16n8k8.row.col.f32.tf32.tf32.f32 "
                 "{%0,%1,%2,%3}, {%4,%5,%6,%7}, {%8,%9}, {%0,%1,%2,%3};"
                 : "+f"(c0), "+f"(c1), "+f"(c2), "+f"(c3)
                 : "r"(a0), "r"(a1), "r"(a2), "r"(a3), "r"(b0), "r"(b1));
}

#define AS_S 20   // uint2 stride per A row (16 + 4 pad) -> conflict-free frag loads
#define BS_S 68   // uint2 stride per B k-row (64 + 4 pad)

template<int NOUT>
__global__ __launch_bounds__(256) void gemm_tc3(const float* __restrict__ b0p, const float* __restrict__ b1p,
                                                const float* __restrict__ b2p, const float* __restrict__ b3p,
                                                int M, int outBase)
{
    constexpr int COLSALL = 4 * NOUT;
    const uint2* __restrict__ gA = (NOUT == 128) ? g_A1 : g_A2;
    const uint2* __restrict__ gW = (NOUT == 128) ? g_Wt1 : g_Wt2;

    int z = blockIdx.z;
    const float* bias = (z == 0) ? b0p : (z == 1) ? b1p : (z == 2) ? b2p : b3p;
    float* C = sel_out(outBase + z);

    __shared__ uint2 As[128 * AS_S];  // [row][k0..15] (hi,lo)
    __shared__ uint2 Bs[16 * BS_S];   // [k0..15][n0..63]

    int tid  = threadIdx.x;
    int lane = tid & 31;
    int w    = tid >> 5;
    int rowW = (w & 3) * 32;
    int colW = (w >> 2) * 32;
    int g = lane >> 2, t = lane & 3;

    int rowBase = blockIdx.y * 128;
    int colBase = z * NOUT + blockIdx.x * 64;   // column in gW's fused [k][4*NOUT] layout
    int colOut  = blockIdx.x * 64;              // column in the output array

    float acc[2][4][4];
    #pragma unroll
    for (int mi = 0; mi < 2; mi++)
        #pragma unroll
        for (int ni = 0; ni < 4; ni++)
            #pragma unroll
            for (int r = 0; r < 4; r++) acc[mi][ni][r] = 0.f;

    for (int kk = 0; kk < 128; kk += 16) {
        // fill As: 128 rows x 16 uint2 = 1024 uint4, 4 per thread
        #pragma unroll
        for (int i = 0; i < 4; i++) {
            int idx = tid + i * 256;            // 0..1023
            int row = idx >> 3;                 // 0..127
            int c2  = (idx & 7) * 2;            // uint2 col 0,2,..,14
            int gr  = rowBase + row;
            uint4 v = make_uint4(0u, 0u, 0u, 0u);
            if (gr < M) v = *(const uint4*)(gA + (size_t)gr * 128 + kk + c2);
            *(uint4*)&As[row * AS_S + c2] = v;
        }
        // fill Bs: 16 k-rows x 64 uint2 = 512 uint4, 2 per thread
        #pragma unroll
        for (int i = 0; i < 2; i++) {
            int idx  = tid + i * 256;           // 0..511
            int krow = idx >> 5;                // 0..15
            int c2   = (idx & 31) * 2;          // uint2 col 0..62
            *(uint4*)&Bs[krow * BS_S + c2] =
                *(const uint4*)(gW + (size_t)(kk + krow) * COLSALL + colBase + c2);
        }
        __syncthreads();

        #pragma unroll
        for (int ks = 0; ks < 2; ks++) {
            int k0 = ks * 8;
            uint2 af[2][4];
            #pragma unroll
            for (int mi = 0; mi < 2; mi++) {
                int r0 = rowW + mi * 16 + g;
                af[mi][0] = As[(r0    ) * AS_S + k0 + t];
                af[mi][1] = As[(r0 + 8) * AS_S + k0 + t];
                af[mi][2] = As[(r0    ) * AS_S + k0 + t + 4];
                af[mi][3] = As[(r0 + 8) * AS_S + k0 + t + 4];
            }
            uint2 bf[4][2];
            #pragma unroll
            for (int ni = 0; ni < 4; ni++) {
                int col = colW + ni * 8 + g;
                bf[ni][0] = Bs[(k0 + t    ) * BS_S + col];
                bf[ni][1] = Bs[(k0 + t + 4) * BS_S + col];
            }
            // 3xTF32: hi*hi + hi*lo + lo*hi
            #pragma unroll
            for (int mi = 0; mi < 2; mi++) {
                #pragma unroll
                for (int ni = 0; ni < 4; ni++) {
                    float* c = acc[mi][ni];
                    mma1688(c[0], c[1], c[2], c[3],
                            af[mi][0].x, af[mi][1].x, af[mi][2].x, af[mi][3].x,
                            bf[ni][0].x, bf[ni][1].x);
                    mma1688(c[0], c[1], c[2], c[3],
                            af[mi][0].x, af[mi][1].x, af[mi][2].x, af[mi][3].x,
                            bf[ni][0].y, bf[ni][1].y);
                    mma1688(c[0], c[1], c[2], c[3],
                            af[mi][0].y, af[mi][1].y, af[mi][2].y, af[mi][3].y,
                            bf[ni][0].x, bf[ni][1].x);
                }
            }
        }
        __syncthreads();
    }

    // epilogue: bias + store
    #pragma unroll
    for (int ni = 0; ni < 4; ni++) {
        int col = colOut + colW + ni * 8 + 2 * t;
        float bx = bias[col], by = bias[col + 1];
        #pragma unroll
        for (int mi = 0; mi < 2; mi++) {
            int r0 = rowBase + rowW + mi * 16 + g;
            float* c = acc[mi][ni];
            if (r0 < M) {
                float2 o = make_float2(c[0] + bx, c[1] + by);
                *(float2*)(C + (size_t)r0 * NOUT + col) = o;
            }
            if (r0 + 8 < M) {
                float2 o = make_float2(c[2] + bx, c[3] + by);
                *(float2*)(C + (size_t)(r0 + 8) * NOUT + col) = o;
            }
        }
    }
}

// ---------------- layer-1 aggregation: warp per node, online softmax, H=8 D=16 ----------------
// 2-deep software pipeline: K/V gathers for edge e+2 issued while computing edge e.
__global__ __launch_bounds__(256) void agg1_kernel(int Nn)
{
    int warp = (blockIdx.x * blockDim.x + threadIdx.x) >> 5;
    int lane = threadIdx.x & 31;
    if (warp >= Nn) return;
    int n = warp;

    const float4* Q4 = (const float4*)g_Q1;
    const float4* K4 = (const float4*)g_K1;
    const float4* V4 = (const float4*)g_V1;
    const float4* S4 = (const float4*)g_S1;

    float4 q = Q4[(size_t)n * 32 + lane];

    int beg = g_rowptr[n];
    int end = g_rowptr[n + 1];

    float m = -1e30f, s = 0.f;
    float4 acc = make_float4(0.f, 0.f, 0.f, 0.f);

    if (beg < end) {
        int s0 = g_psrc[beg];
        float4 kA = K4[(size_t)s0 * 32 + lane];
        float4 vA = V4[(size_t)s0 * 32 + lane];
        float4 kB = kA, vB = vA;
        if (beg + 1 < end) {
            int s1 = g_psrc[beg + 1];
            kB = K4[(size_t)s1 * 32 + lane];
            vB = V4[(size_t)s1 * 32 + lane];
        }
        for (int e = beg; e < end; e++) {
            float4 kC = kA, vC = vA;
            if (e + 2 < end) {
                int s2 = g_psrc[e + 2];
                kC = K4[(size_t)s2 * 32 + lane];
                vC = V4[(size_t)s2 * 32 + lane];
            }

            float d = kA.x * q.x + kA.y * q.y + kA.z * q.z + kA.w * q.w;
            d += __shfl_xor_sync(0xffffffffu, d, 1);
            d += __shfl_xor_sync(0xffffffffu, d, 2);
            float sc = d * 0.25f;

            float mn = fmaxf(m, sc);
            float c  = __expf(m - mn);
            float p  = __expf(sc - mn);
            s = s * c + p;
            acc.x = acc.x * c + p * vA.x;
            acc.y = acc.y * c + p * vA.y;
            acc.z = acc.z * c + p * vA.z;
            acc.w = acc.w * c + p * vA.w;
            m = mn;

            kA = kB; vA = vB; kB = kC; vB = vC;
        }
    }

    float inv = 1.f / (s + 1e-16f);
    float4 sk = S4[(size_t)n * 32 + lane];
    float4 o;
    o.x = fmaxf(acc.x * inv + sk.x, 0.f);
    o.y = fmaxf(acc.y * inv + sk.y, 0.f);
    o.z = fmaxf(acc.z * inv + sk.z, 0.f);
    o.w = fmaxf(acc.w * inv + sk.w, 0.f);
    ((float4*)g_h)[(size_t)n * 32 + lane] = o;
}

// ---------------- layer-2 aggregation: warp per node, online softmax, H=1 D=64 ----------------
__global__ __launch_bounds__(256) void agg2_kernel(float* __restrict__ out, int Nn)
{
    int warp = (blockIdx.x * blockDim.x + threadIdx.x) >> 5;
    int lane = threadIdx.x & 31;
    if (warp >= Nn) return;
    int n = warp;

    const float2* Q2 = (const float2*)g_Q2;
    const float2* K2 = (const float2*)g_K2;
    const float2* V2 = (const float2*)g_V2;
    const float2* S2 = (const float2*)g_S2;

    float2 q = Q2[(size_t)n * 32 + lane];

    int beg = g_rowptr[n];
    int end = g_rowptr[n + 1];

    float m = -1e30f, s = 0.f;
    float2 acc = make_float2(0.f, 0.f);

    if (beg < end) {
        int s0 = g_psrc[beg];
        float2 kA = K2[(size_t)s0 * 32 + lane];
        float2 vA = V2[(size_t)s0 * 32 + lane];
        float2 kB = kA, vB = vA;
        if (beg + 1 < end) {
            int s1 = g_psrc[beg + 1];
            kB = K2[(size_t)s1 * 32 + lane];
            vB = V2[(size_t)s1 * 32 + lane];
        }
        for (int e = beg; e < end; e++) {
            float2 kC = kA, vC = vA;
            if (e + 2 < end) {
                int s2 = g_psrc[e + 2];
                kC = K2[(size_t)s2 * 32 + lane];
                vC = V2[(size_t)s2 * 32 + lane];
            }

            float d = kA.x * q.x + kA.y * q.y;
            #pragma unroll
            for (int off = 16; off > 0; off >>= 1)
                d += __shfl_xor_sync(0xffffffffu, d, off);
            float sc = d * 0.125f;

            float mn = fmaxf(m, sc);
            float c  = __expf(m - mn);
            float p  = __expf(sc - mn);
            s = s * c + p;
            acc.x = acc.x * c + p * vA.x;
            acc.y = acc.y * c + p * vA.y;
            m = mn;

            kA = kB; vA = vB; kB = kC; vB = vC;
        }
    }

    float inv = 1.f / (s + 1e-16f);
    float2 sk = S2[(size_t)n * 32 + lane];
    float2 o;
    o.x = acc.x * inv + sk.x;
    o.y = acc.y * inv + sk.y;
    ((float2*)out)[(size_t)n * 32 + lane] = o;
}

// ---------------- launch ----------------
extern "C" void kernel_launch(void* const* d_in, const int* in_sizes, int n_in,
                              void* d_out, int out_size)
{
    const float* x   = (const float*)d_in[0];
    const float* Wq1 = (const float*)d_in[1];  const float* bq1 = (const float*)d_in[2];
    const float* Wk1 = (const float*)d_in[3];  const float* bk1 = (const float*)d_in[4];
    const float* Wv1 = (const float*)d_in[5];  const float* bv1 = (const float*)d_in[6];
    const float* Ws1 = (const float*)d_in[7];  const float* bs1 = (const float*)d_in[8];
    const float* Wq2 = (const float*)d_in[9];  const float* bq2 = (const float*)d_in[10];
    const float* Wk2 = (const float*)d_in[11]; const float* bk2 = (const float*)d_in[12];
    const float* Wv2 = (const float*)d_in[13]; const float* bv2 = (const float*)d_in[14];
    const float* Ws2 = (const float*)d_in[15]; const float* bs2 = (const float*)d_in[16];
    const int* esrc  = (const int*)d_in[17];
    const int* edst  = (const int*)d_in[18];
    float* out = (float*)d_out;

    int Nn = in_sizes[0] / 128;
    int E  = in_sizes[17];

    // CSR build
    k_zero<<<(Nn + 255) / 256, 256>>>(Nn);
    k_hist<<<(E + 255) / 256, 256>>>(edst, E);
    k_scan<<<1, 1024>>>(Nn);
    k_scatter<<<(E + 255) / 256, 256>>>(esrc, edst, E);

    // tf32 split prep
    int totA = Nn * 128;
    k_splitA<<<(totA + 255) / 256, 256>>>(x, totA, 0);
    k_splitW<<<(4 * 128 * 128 + 255) / 256, 256>>>(Wq1, Wk1, Wv1, Ws1, 128, 0);
    k_splitW<<<(4 * 128 * 64 + 255) / 256, 256>>>(Wq2, Wk2, Wv2, Ws2, 64, 1);

    int rowBlocks = (Nn + 127) / 128;

    // layer-1 projections: grid (2 col-tiles, rowBlocks, 4 outputs)
    dim3 g1(2, rowBlocks, 4);
    gemm_tc3<128><<<g1, 256>>>(bq1, bk1, bv1, bs1, Nn, 0);

    int aggBlocks = (Nn + 7) / 8;
    agg1_kernel<<<aggBlocks, 256>>>(Nn);

    // split hidden for layer-2 A
    k_splitA<<<(totA + 255) / 256, 256>>>(nullptr, totA, 1);

    // layer-2 projections: grid (1, rowBlocks, 4)
    dim3 g2(1, rowBlocks, 4);
    gemm_tc3<64><<<g2, 256>>>(bq2, bk2, bv2, bs2, Nn, 4);

    agg2_kernel<<<aggBlocks, 256>>>(out, Nn);
}

// round 14
// speedup vs baseline: 1.3721x; 1.0802x over previous
#include <cuda_runtime.h>
#include <cuda_bf16.h>
#include <cstdint>

// Problem constants (fixed shapes per reference)
#define NN_MAX 50000
#define EE_MAX 800000

// ---------------- scratch (device globals; no runtime allocation) ----------------
__device__ __align__(16) float g_Q1[NN_MAX * 128];
__device__ __align__(16) float g_K1[NN_MAX * 128];
__device__ __align__(16) float g_V1[NN_MAX * 128];
__device__ __align__(16) float g_S1[NN_MAX * 128];
__device__ __align__(16) float g_h [NN_MAX * 128];
__device__ __align__(16) float g_Q2[NN_MAX * 64];
__device__ __align__(16) float g_K2[NN_MAX * 64];
__device__ __align__(16) float g_V2[NN_MAX * 64];
__device__ __align__(16) float g_S2[NN_MAX * 64];

__device__ int g_cnt[NN_MAX];
__device__ int g_rowptr[NN_MAX + 1];
__device__ int g_cur[NN_MAX];
__device__ int g_psrc[EE_MAX];

// ---------------- CSR build ----------------
__global__ void k_zero(int n) {
    int i = blockIdx.x * blockDim.x + threadIdx.x;
    if (i < n) g_cnt[i] = 0;
}

__global__ void k_hist(const int* __restrict__ dst, int e) {
    int i = blockIdx.x * blockDim.x + threadIdx.x;
    if (i < e) atomicAdd(&g_cnt[dst[i]], 1);
}

__global__ __launch_bounds__(1024) void k_scan(int n) {
    int tid = threadIdx.x;
    int CH = (n + 1023) >> 10;
    int base = tid * CH;
    int lim = min(base + CH, n);

    int sum = 0;
    for (int i = base; i < lim; i++) sum += g_cnt[i];

    int lane = tid & 31, wid = tid >> 5;
    int v = sum;
    #pragma unroll
    for (int off = 1; off < 32; off <<= 1) {
        int t = __shfl_up_sync(0xffffffffu, v, off);
        if (lane >= off) v += t;
    }
    __shared__ int wsum[32];
    if (lane == 31) wsum[wid] = v;
    __syncthreads();
    if (wid == 0) {
        int w = wsum[lane];
        #pragma unroll
        for (int off = 1; off < 32; off <<= 1) {
            int t = __shfl_up_sync(0xffffffffu, w, off);
            if (lane >= off) w += t;
        }
        wsum[lane] = w;
    }
    __syncthreads();
    int excl = v - sum + (wid ? wsum[wid - 1] : 0);

    int run = excl;
    for (int i = base; i < lim; i++) {
        int c = g_cnt[i];
        g_rowptr[i] = run;
        g_cur[i] = run;
        run += c;
    }
    if (tid == 1023) g_rowptr[n] = run;
}

__global__ void k_scatter(const int* __restrict__ src, const int* __restrict__ dst, int e) {
    int i = blockIdx.x * blockDim.x + threadIdx.x;
    if (i < e) {
        int d = dst[i];
        int pos = atomicAdd(&g_cur[d], 1);
        g_psrc[pos] = src[i];
    }
}

// ---------------- tensor-core GEMM (R3 config): (M x 128) @ (128 x Ncols) + bias ----------------
// split-tf32 (3xTF32): x = hi + lo, C = Ah*Bh + Ah*Bl + Al*Bh  (fp32-class accuracy)
// Tile: BM=128, BN=64, BK=16. 256 threads = 8 warps (4 row x 2 col), warp tile 32x32.

__device__ __forceinline__ float* sel_out(int s) {
    switch (s) {
        case 0: return g_Q1; case 1: return g_K1; case 2: return g_V1; case 3: return g_S1;
        case 4: return g_Q2; case 5: return g_K2; case 6: return g_V2; default: return g_S2;
    }
}

__device__ __forceinline__ unsigned f2tf(float x) {
    unsigned r;
    asm("cvt.rna.tf32.f32 %0, %1;" : "=r"(r) : "f"(x));
    return r;
}

__device__ __forceinline__ uint2 split_tf32(float x) {
    unsigned hi = f2tf(x);
    float lof = x - __uint_as_float(hi);
    unsigned lo = f2tf(lof);
    return make_uint2(hi, lo);
}

__device__ __forceinline__ void mma1688(float& c0, float& c1, float& c2, float& c3,
                                        unsigned a0, unsigned a1, unsigned a2, unsigned a3,
                                        unsigned b0, unsigned b1) {
    asm volatile("mma.sync.aligned.m16n8k8.row.col.f32.tf32.tf32.f32 "
                 "{%0,%1,%2,%3}, {%4,%5,%6,%7}, {%8,%9}, {%0,%1,%2,%3};"
                 : "+f"(c0), "+f"(c1), "+f"(c2), "+f"(c3)
                 : "r"(a0), "r"(a1), "r"(a2), "r"(a3), "r"(b0), "r"(b1));
}

#define AS_S 20   // float2-unit stride, 2*S%32==8 -> conflict-free frag loads
#define BS_S 68   // float2-unit stride, 2*S%32==8

__global__ __launch_bounds__(256) void gemm_tc(const float* __restrict__ Ain,
                                               const float* __restrict__ W0, const float* __restrict__ W1,
                                               const float* __restrict__ W2, const float* __restrict__ W3,
                                               const float* __restrict__ b0p, const float* __restrict__ b1p,
                                               const float* __restrict__ b2p, const float* __restrict__ b3p,
                                               int M, int Ncols, int outBase)
{
    const float* A = Ain ? Ain : g_h;
    int z = blockIdx.z;
    const float* W    = (z == 0) ? W0  : (z == 1) ? W1  : (z == 2) ? W2  : W3;
    const float* bias = (z == 0) ? b0p : (z == 1) ? b1p : (z == 2) ? b2p : b3p;
    float* C = sel_out(outBase + z);

    __shared__ uint2 As[128 * AS_S];  // [row][k0..15] hi/lo interleaved
    __shared__ uint2 Bs[16 * BS_S];   // [k0..15][n0..63]

    int tid  = threadIdx.x;
    int lane = tid & 31;
    int w    = tid >> 5;
    int rowW = (w & 3) * 32;
    int colW = (w >> 2) * 32;
    int g = lane >> 2, t = lane & 3;

    int rowBase = blockIdx.y * 128;
    int colBase = blockIdx.x * 64;

    float acc[2][4][4];
    #pragma unroll
    for (int mi = 0; mi < 2; mi++)
        #pragma unroll
        for (int ni = 0; ni < 4; ni++)
            #pragma unroll
            for (int r = 0; r < 4; r++) acc[mi][ni][r] = 0.f;

    for (int kk = 0; kk < 128; kk += 16) {
        // fill As: 128x16 floats = 512 float4, 2 per thread
        #pragma unroll
        for (int i = 0; i < 2; i++) {
            int idx = tid + i * 256;           // 0..511
            int row = idx >> 2;                // 0..127
            int c4  = (idx & 3) * 4;           // 0,4,8,12
            int gr  = rowBase + row;
            float4 av = make_float4(0.f, 0.f, 0.f, 0.f);
            if (gr < M) av = *(const float4*)(A + (size_t)gr * 128 + kk + c4);
            As[row * AS_S + c4 + 0] = split_tf32(av.x);
            As[row * AS_S + c4 + 1] = split_tf32(av.y);
            As[row * AS_S + c4 + 2] = split_tf32(av.z);
            As[row * AS_S + c4 + 3] = split_tf32(av.w);
        }
        // fill Bs: 16x64 floats = 256 float4, 1 per thread
        {
            int idx  = tid;                    // 0..255
            int krow = idx >> 4;               // 0..15
            int c4   = (idx & 15) * 4;         // 0..60
            float4 bv = *(const float4*)(W + (size_t)(kk + krow) * Ncols + colBase + c4);
            Bs[krow * BS_S + c4 + 0] = split_tf32(bv.x);
            Bs[krow * BS_S + c4 + 1] = split_tf32(bv.y);
            Bs[krow * BS_S + c4 + 2] = split_tf32(bv.z);
            Bs[krow * BS_S + c4 + 3] = split_tf32(bv.w);
        }
        __syncthreads();

        #pragma unroll
        for (int ks = 0; ks < 2; ks++) {
            int k0 = ks * 8;
            uint2 af[2][4];
            #pragma unroll
            for (int mi = 0; mi < 2; mi++) {
                int r0 = rowW + mi * 16 + g;
                af[mi][0] = As[(r0    ) * AS_S + k0 + t];
                af[mi][1] = As[(r0 + 8) * AS_S + k0 + t];
                af[mi][2] = As[(r0    ) * AS_S + k0 + t + 4];
                af[mi][3] = As[(r0 + 8) * AS_S + k0 + t + 4];
            }
            uint2 bf[4][2];
            #pragma unroll
            for (int ni = 0; ni < 4; ni++) {
                int col = colW + ni * 8 + g;
                bf[ni][0] = Bs[(k0 + t    ) * BS_S + col];
                bf[ni][1] = Bs[(k0 + t + 4) * BS_S + col];
            }
            // 3xTF32 mma: hi*hi + hi*lo + lo*hi
            #pragma unroll
            for (int mi = 0; mi < 2; mi++) {
                #pragma unroll
                for (int ni = 0; ni < 4; ni++) {
                    float* c = acc[mi][ni];
                    mma1688(c[0], c[1], c[2], c[3],
                            af[mi][0].x, af[mi][1].x, af[mi][2].x, af[mi][3].x,
                            bf[ni][0].x, bf[ni][1].x);
                    mma1688(c[0], c[1], c[2], c[3],
                            af[mi][0].x, af[mi][1].x, af[mi][2].x, af[mi][3].x,
                            bf[ni][0].y, bf[ni][1].y);
                    mma1688(c[0], c[1], c[2], c[3],
                            af[mi][0].y, af[mi][1].y, af[mi][2].y, af[mi][3].y,
                            bf[ni][0].x, bf[ni][1].x);
                }
            }
        }
        __syncthreads();
    }

    // epilogue: bias + store (float2 per c-pair)
    #pragma unroll
    for (int ni = 0; ni < 4; ni++) {
        int col = colBase + colW + ni * 8 + 2 * t;
        float bx = bias[col], by = bias[col + 1];
        #pragma unroll
        for (int mi = 0; mi < 2; mi++) {
            int r0 = rowBase + rowW + mi * 16 + g;
            float* c = acc[mi][ni];
            if (r0 < M) {
                float2 o = make_float2(c[0] + bx, c[1] + by);
                *(float2*)(C + (size_t)r0 * Ncols + col) = o;
            }
            if (r0 + 8 < M) {
                float2 o = make_float2(c[2] + bx, c[3] + by);
                *(float2*)(C + (size_t)(r0 + 8) * Ncols + col) = o;
            }
        }
    }
}

// ---------------- layer-1 aggregation: warp per node, online softmax, H=8 D=16 ----------------
// Chunk-of-4 batched gathers: 8 independent LDG.128 in flight per chunk (MLP 8).
__global__ __launch_bounds__(256) void agg1_kernel(int Nn)
{
    int warp = (blockIdx.x * blockDim.x + threadIdx.x) >> 5;
    int lane = threadIdx.x & 31;
    if (warp >= Nn) return;
    int n = warp;

    const float4* Q4 = (const float4*)g_Q1;
    const float4* K4 = (const float4*)g_K1;
    const float4* V4 = (const float4*)g_V1;
    const float4* S4 = (const float4*)g_S1;

    float4 q = Q4[(size_t)n * 32 + lane];   // lane holds dims 4*lane..4*lane+3; head = lane>>2

    int beg = g_rowptr[n];
    int end = g_rowptr[n + 1];

    float m = -1e30f, s = 0.f;
    float4 acc = make_float4(0.f, 0.f, 0.f, 0.f);

    for (int e = beg; e < end; e += 4) {
        int cnt = end - e;          // >=1 inside loop
        float4 kb[4], vb[4];
        // batched gather: all loads issued before any compute
        #pragma unroll
        for (int i = 0; i < 4; i++) {
            if (i < cnt) {
                int src = g_psrc[e + i];
                kb[i] = K4[(size_t)src * 32 + lane];
                vb[i] = V4[(size_t)src * 32 + lane];
            }
        }
        #pragma unroll
        for (int i = 0; i < 4; i++) {
            if (i < cnt) {
                float d = kb[i].x * q.x + kb[i].y * q.y + kb[i].z * q.z + kb[i].w * q.w;
                d += __shfl_xor_sync(0xffffffffu, d, 1);
                d += __shfl_xor_sync(0xffffffffu, d, 2);   // reduce within 4-lane head group
                float sc = d * 0.25f;                       // 1/sqrt(16)

                float mn = fmaxf(m, sc);
                float c  = __expf(m - mn);
                float p  = __expf(sc - mn);
                s = s * c + p;
                acc.x = acc.x * c + p * vb[i].x;
                acc.y = acc.y * c + p * vb[i].y;
                acc.z = acc.z * c + p * vb[i].z;
                acc.w = acc.w * c + p * vb[i].w;
                m = mn;
            }
        }
    }

    float inv = 1.f / (s + 1e-16f);
    float4 sk = S4[(size_t)n * 32 + lane];
    float4 o;
    o.x = fmaxf(acc.x * inv + sk.x, 0.f);
    o.y = fmaxf(acc.y * inv + sk.y, 0.f);
    o.z = fmaxf(acc.z * inv + sk.z, 0.f);
    o.w = fmaxf(acc.w * inv + sk.w, 0.f);
    ((float4*)g_h)[(size_t)n * 32 + lane] = o;
}

// ---------------- layer-2 aggregation: warp per node, online softmax, H=1 D=64 ----------------
__global__ __launch_bounds__(256) void agg2_kernel(float* __restrict__ out, int Nn)
{
    int warp = (blockIdx.x * blockDim.x + threadIdx.x) >> 5;
    int lane = threadIdx.x & 31;
    if (warp >= Nn) return;
    int n = warp;

    const float2* Q2 = (const float2*)g_Q2;
    const float2* K2 = (const float2*)g_K2;
    const float2* V2 = (const float2*)g_V2;
    const float2* S2 = (const float2*)g_S2;

    float2 q = Q2[(size_t)n * 32 + lane];   // lane holds dims 2*lane..2*lane+1

    int beg = g_rowptr[n];
    int end = g_rowptr[n + 1];

    float m = -1e30f, s = 0.f;
    float2 acc = make_float2(0.f, 0.f);

    for (int e = beg; e < end; e += 4) {
        int cnt = end - e;
        float2 kb[4], vb[4];
        #pragma unroll
        for (int i = 0; i < 4; i++) {
            if (i < cnt) {
                int src = g_psrc[e + i];
                kb[i] = K2[(size_t)src * 32 + lane];
                vb[i] = V2[(size_t)src * 32 + lane];
            }
        }
        #pragma unroll
        for (int i = 0; i < 4; i++) {
            if (i < cnt) {
                float d = kb[i].x * q.x + kb[i].y * q.y;
                #pragma unroll
                for (int off = 16; off > 0; off >>= 1)
                    d += __shfl_xor_sync(0xffffffffu, d, off);
                float sc = d * 0.125f;                      // 1/sqrt(64)

                float mn = fmaxf(m, sc);
                float c  = __expf(m - mn);
                float p  = __expf(sc - mn);
                s = s * c + p;
                acc.x = acc.x * c + p * vb[i].x;
                acc.y = acc.y * c + p * vb[i].y;
                m = mn;
            }
        }
    }

    float inv = 1.f / (s + 1e-16f);
    float2 sk = S2[(size_t)n * 32 + lane];
    float2 o;
    o.x = acc.x * inv + sk.x;
    o.y = acc.y * inv + sk.y;
    ((float2*)out)[(size_t)n * 32 + lane] = o;
}

// ---------------- launch ----------------
extern "C" void kernel_launch(void* const* d_in, const int* in_sizes, int n_in,
                              void* d_out, int out_size)
{
    const float* x   = (const float*)d_in[0];
    const float* Wq1 = (const float*)d_in[1];  const float* bq1 = (const float*)d_in[2];
    const float* Wk1 = (const float*)d_in[3];  const float* bk1 = (const float*)d_in[4];
    const float* Wv1 = (const float*)d_in[5];  const float* bv1 = (const float*)d_in[6];
    const float* Ws1 = (const float*)d_in[7];  const float* bs1 = (const float*)d_in[8];
    const float* Wq2 = (const float*)d_in[9];  const float* bq2 = (const float*)d_in[10];
    const float* Wk2 = (const float*)d_in[11]; const float* bk2 = (const float*)d_in[12];
    const float* Wv2 = (const float*)d_in[13]; const float* bv2 = (const float*)d_in[14];
    const float* Ws2 = (const float*)d_in[15]; const float* bs2 = (const float*)d_in[16];
    const int* esrc  = (const int*)d_in[17];
    const int* edst  = (const int*)d_in[18];
    float* out = (float*)d_out;

    int Nn = in_sizes[0] / 128;
    int E  = in_sizes[17];

    // CSR build (per launch; replayed identically by the graph)
    k_zero<<<(Nn + 255) / 256, 256>>>(Nn);
    k_hist<<<(E + 255) / 256, 256>>>(edst, E);
    k_scan<<<1, 1024>>>(Nn);
    k_scatter<<<(E + 255) / 256, 256>>>(esrc, edst, E);

    // layer-1 projections: [N,128] @ [128,128] + b   (Q,K,V,S via blockIdx.z)
    dim3 g1(2, (Nn + 127) / 128, 4);
    gemm_tc<<<g1, 256>>>(x, Wq1, Wk1, Wv1, Ws1, bq1, bk1, bv1, bs1, Nn, 128, 0);

    int aggBlocks = (Nn + 7) / 8;   // 8 warps per 256-thread block
    agg1_kernel<<<aggBlocks, 256>>>(Nn);

    // layer-2 projections: [N,128] @ [128,64] + b (A = g_h via nullptr)
    dim3 g2(1, (Nn + 127) / 128, 4);
    gemm_tc<<<g2, 256>>>(nullptr, Wq2, Wk2, Wv2, Ws2, bq2, bk2, bv2, bs2, Nn, 64, 4);

    agg2_kernel<<<aggBlocks, 256>>>(out, Nn);
}

// round 15
// speedup vs baseline: 1.3895x; 1.0127x over previous
#include <cuda_runtime.h>
#include <cuda_bf16.h>
#include <cstdint>

// Problem constants (fixed shapes per reference)
#define NN_MAX 50000
#define EE_MAX 800000

// ---------------- scratch (device globals; no runtime allocation) ----------------
__device__ __align__(16) float g_Q1[NN_MAX * 128];
__device__ __align__(16) float g_K1[NN_MAX * 128];
__device__ __align__(16) float g_V1[NN_MAX * 128];
__device__ __align__(16) float g_S1[NN_MAX * 128];
__device__ __align__(16) float g_h [NN_MAX * 128];
__device__ __align__(16) float g_Q2[NN_MAX * 64];
__device__ __align__(16) float g_K2[NN_MAX * 64];
__device__ __align__(16) float g_V2[NN_MAX * 64];
__device__ __align__(16) float g_S2[NN_MAX * 64];

__device__ int g_cnt[NN_MAX];
__device__ int g_rowptr[NN_MAX + 1];
__device__ int g_cur[NN_MAX];
__device__ int g_psrc[EE_MAX];

// ---------------- CSR build ----------------
__global__ void k_zero(int n) {
    int i = blockIdx.x * blockDim.x + threadIdx.x;
    if (i < n) g_cnt[i] = 0;
}

__global__ void k_hist(const int* __restrict__ dst, int e) {
    int i = blockIdx.x * blockDim.x + threadIdx.x;
    if (i < e) atomicAdd(&g_cnt[dst[i]], 1);
}

__global__ __launch_bounds__(1024) void k_scan(int n) {
    int tid = threadIdx.x;
    int CH = (n + 1023) >> 10;
    int base = tid * CH;
    int lim = min(base + CH, n);

    int sum = 0;
    for (int i = base; i < lim; i++) sum += g_cnt[i];

    int lane = tid & 31, wid = tid >> 5;
    int v = sum;
    #pragma unroll
    for (int off = 1; off < 32; off <<= 1) {
        int t = __shfl_up_sync(0xffffffffu, v, off);
        if (lane >= off) v += t;
    }
    __shared__ int wsum[32];
    if (lane == 31) wsum[wid] = v;
    __syncthreads();
    if (wid == 0) {
        int w = wsum[lane];
        #pragma unroll
        for (int off = 1; off < 32; off <<= 1) {
            int t = __shfl_up_sync(0xffffffffu, w, off);
            if (lane >= off) w += t;
        }
        wsum[lane] = w;
    }
    __syncthreads();
    int excl = v - sum + (wid ? wsum[wid - 1] : 0);

    int run = excl;
    for (int i = base; i < lim; i++) {
        int c = g_cnt[i];
        g_rowptr[i] = run;
        g_cur[i] = run;
        run += c;
    }
    if (tid == 1023) g_rowptr[n] = run;
}

__global__ void k_scatter(const int* __restrict__ src, const int* __restrict__ dst, int e) {
    int i = blockIdx.x * blockDim.x + threadIdx.x;
    if (i < e) {
        int d = dst[i];
        int pos = atomicAdd(&g_cur[d], 1);
        g_psrc[pos] = src[i];
    }
}

// ---------------- tensor-core GEMM (R3 config): (M x 128) @ (128 x Ncols) + bias ----------------
// split-tf32 (3xTF32): x = hi + lo, C = Ah*Bh + Ah*Bl + Al*Bh  (fp32-class accuracy)
// Tile: BM=128, BN=64, BK=16. 256 threads = 8 warps (4 row x 2 col), warp tile 32x32.

__device__ __forceinline__ float* sel_out(int s) {
    switch (s) {
        case 0: return g_Q1; case 1: return g_K1; case 2: return g_V1; case 3: return g_S1;
        case 4: return g_Q2; case 5: return g_K2; case 6: return g_V2; default: return g_S2;
    }
}

__device__ __forceinline__ unsigned f2tf(float x) {
    unsigned r;
    asm("cvt.rna.tf32.f32 %0, %1;" : "=r"(r) : "f"(x));
    return r;
}

__device__ __forceinline__ uint2 split_tf32(float x) {
    unsigned hi = f2tf(x);
    float lof = x - __uint_as_float(hi);
    unsigned lo = f2tf(lof);
    return make_uint2(hi, lo);
}

__device__ __forceinline__ void mma1688(float& c0, float& c1, float& c2, float& c3,
                                        unsigned a0, unsigned a1, unsigned a2, unsigned a3,
                                        unsigned b0, unsigned b1) {
    asm volatile("mma.sync.aligned.m16n8k8.row.col.f32.tf32.tf32.f32 "
                 "{%0,%1,%2,%3}, {%4,%5,%6,%7}, {%8,%9}, {%0,%1,%2,%3};"
                 : "+f"(c0), "+f"(c1), "+f"(c2), "+f"(c3)
                 : "r"(a0), "r"(a1), "r"(a2), "r"(a3), "r"(b0), "r"(b1));
}

#define AS_S 20   // float2-unit stride, 2*S%32==8 -> conflict-free frag loads
#define BS_S 68   // float2-unit stride, 2*S%32==8

__global__ __launch_bounds__(256) void gemm_tc(const float* __restrict__ Ain,
                                               const float* __restrict__ W0, const float* __restrict__ W1,
                                               const float* __restrict__ W2, const float* __restrict__ W3,
                                               const float* __restrict__ b0p, const float* __restrict__ b1p,
                                               const float* __restrict__ b2p, const float* __restrict__ b3p,
                                               int M, int Ncols, int outBase)
{
    const float* A = Ain ? Ain : g_h;
    int z = blockIdx.z;
    const float* W    = (z == 0) ? W0  : (z == 1) ? W1  : (z == 2) ? W2  : W3;
    const float* bias = (z == 0) ? b0p : (z == 1) ? b1p : (z == 2) ? b2p : b3p;
    float* C = sel_out(outBase + z);

    __shared__ uint2 As[128 * AS_S];  // [row][k0..15] hi/lo interleaved
    __shared__ uint2 Bs[16 * BS_S];   // [k0..15][n0..63]

    int tid  = threadIdx.x;
    int lane = tid & 31;
    int w    = tid >> 5;
    int rowW = (w & 3) * 32;
    int colW = (w >> 2) * 32;
    int g = lane >> 2, t = lane & 3;

    int rowBase = blockIdx.y * 128;
    int colBase = blockIdx.x * 64;

    float acc[2][4][4];
    #pragma unroll
    for (int mi = 0; mi < 2; mi++)
        #pragma unroll
        for (int ni = 0; ni < 4; ni++)
            #pragma unroll
            for (int r = 0; r < 4; r++) acc[mi][ni][r] = 0.f;

    for (int kk = 0; kk < 128; kk += 16) {
        // fill As: 128x16 floats = 512 float4, 2 per thread
        #pragma unroll
        for (int i = 0; i < 2; i++) {
            int idx = tid + i * 256;           // 0..511
            int row = idx >> 2;                // 0..127
            int c4  = (idx & 3) * 4;           // 0,4,8,12
            int gr  = rowBase + row;
            float4 av = make_float4(0.f, 0.f, 0.f, 0.f);
            if (gr < M) av = *(const float4*)(A + (size_t)gr * 128 + kk + c4);
            As[row * AS_S + c4 + 0] = split_tf32(av.x);
            As[row * AS_S + c4 + 1] = split_tf32(av.y);
            As[row * AS_S + c4 + 2] = split_tf32(av.z);
            As[row * AS_S + c4 + 3] = split_tf32(av.w);
        }
        // fill Bs: 16x64 floats = 256 float4, 1 per thread
        {
            int idx  = tid;                    // 0..255
            int krow = idx >> 4;               // 0..15
            int c4   = (idx & 15) * 4;         // 0..60
            float4 bv = *(const float4*)(W + (size_t)(kk + krow) * Ncols + colBase + c4);
            Bs[krow * BS_S + c4 + 0] = split_tf32(bv.x);
            Bs[krow * BS_S + c4 + 1] = split_tf32(bv.y);
            Bs[krow * BS_S + c4 + 2] = split_tf32(bv.z);
            Bs[krow * BS_S + c4 + 3] = split_tf32(bv.w);
        }
        __syncthreads();

        #pragma unroll
        for (int ks = 0; ks < 2; ks++) {
            int k0 = ks * 8;
            uint2 af[2][4];
            #pragma unroll
            for (int mi = 0; mi < 2; mi++) {
                int r0 = rowW + mi * 16 + g;
                af[mi][0] = As[(r0    ) * AS_S + k0 + t];
                af[mi][1] = As[(r0 + 8) * AS_S + k0 + t];
                af[mi][2] = As[(r0    ) * AS_S + k0 + t + 4];
                af[mi][3] = As[(r0 + 8) * AS_S + k0 + t + 4];
            }
            uint2 bf[4][2];
            #pragma unroll
            for (int ni = 0; ni < 4; ni++) {
                int col = colW + ni * 8 + g;
                bf[ni][0] = Bs[(k0 + t    ) * BS_S + col];
                bf[ni][1] = Bs[(k0 + t + 4) * BS_S + col];
            }
            // 3xTF32 mma: hi*hi + hi*lo + lo*hi
            #pragma unroll
            for (int mi = 0; mi < 2; mi++) {
                #pragma unroll
                for (int ni = 0; ni < 4; ni++) {
                    float* c = acc[mi][ni];
                    mma1688(c[0], c[1], c[2], c[3],
                            af[mi][0].x, af[mi][1].x, af[mi][2].x, af[mi][3].x,
                            bf[ni][0].x, bf[ni][1].x);
                    mma1688(c[0], c[1], c[2], c[3],
                            af[mi][0].x, af[mi][1].x, af[mi][2].x, af[mi][3].x,
                            bf[ni][0].y, bf[ni][1].y);
                    mma1688(c[0], c[1], c[2], c[3],
                            af[mi][0].y, af[mi][1].y, af[mi][2].y, af[mi][3].y,
                            bf[ni][0].x, bf[ni][1].x);
                }
            }
        }
        __syncthreads();
    }

    // epilogue: bias + store (float2 per c-pair)
    #pragma unroll
    for (int ni = 0; ni < 4; ni++) {
        int col = colBase + colW + ni * 8 + 2 * t;
        float bx = bias[col], by = bias[col + 1];
        #pragma unroll
        for (int mi = 0; mi < 2; mi++) {
            int r0 = rowBase + rowW + mi * 16 + g;
            float* c = acc[mi][ni];
            if (r0 < M) {
                float2 o = make_float2(c[0] + bx, c[1] + by);
                *(float2*)(C + (size_t)r0 * Ncols + col) = o;
            }
            if (r0 + 8 < M) {
                float2 o = make_float2(c[2] + bx, c[3] + by);
                *(float2*)(C + (size_t)(r0 + 8) * Ncols + col) = o;
            }
        }
    }
}

// ---------------- layer-1 aggregation: warp per node, online softmax, H=8 D=16 ----------------
__global__ __launch_bounds__(256) void agg1_kernel(int Nn)
{
    int warp = (blockIdx.x * blockDim.x + threadIdx.x) >> 5;
    int lane = threadIdx.x & 31;
    if (warp >= Nn) return;
    int n = warp;

    const float4* Q4 = (const float4*)g_Q1;
    const float4* K4 = (const float4*)g_K1;
    const float4* V4 = (const float4*)g_V1;
    const float4* S4 = (const float4*)g_S1;

    float4 q = Q4[(size_t)n * 32 + lane];   // lane holds dims 4*lane..4*lane+3; head = lane>>2

    int beg = g_rowptr[n];
    int end = g_rowptr[n + 1];

    float m = -1e30f, s = 0.f;
    float4 acc = make_float4(0.f, 0.f, 0.f, 0.f);

    if (beg < end) {
        int src = g_psrc[beg];
        float4 kk = K4[(size_t)src * 32 + lane];
        float4 vv = V4[(size_t)src * 32 + lane];
        for (int e = beg; e < end; e++) {
            int nsrc = (e + 1 < end) ? g_psrc[e + 1] : src;
            float4 nk = K4[(size_t)nsrc * 32 + lane];
            float4 nv = V4[(size_t)nsrc * 32 + lane];

            float d = kk.x * q.x + kk.y * q.y + kk.z * q.z + kk.w * q.w;
            d += __shfl_xor_sync(0xffffffffu, d, 1);
            d += __shfl_xor_sync(0xffffffffu, d, 2);   // reduced within 4-lane head group
            float sc = d * 0.25f;                       // 1/sqrt(16)

            float mn = fmaxf(m, sc);
            float c  = __expf(m - mn);
            float p  = __expf(sc - mn);
            s = s * c + p;
            acc.x = acc.x * c + p * vv.x;
            acc.y = acc.y * c + p * vv.y;
            acc.z = acc.z * c + p * vv.z;
            acc.w = acc.w * c + p * vv.w;
            m = mn;

            kk = nk; vv = nv;
        }
    }

    float inv = 1.f / (s + 1e-16f);
    float4 sk = S4[(size_t)n * 32 + lane];
    float4 o;
    o.x = fmaxf(acc.x * inv + sk.x, 0.f);
    o.y = fmaxf(acc.y * inv + sk.y, 0.f);
    o.z = fmaxf(acc.z * inv + sk.z, 0.f);
    o.w = fmaxf(acc.w * inv + sk.w, 0.f);
    ((float4*)g_h)[(size_t)n * 32 + lane] = o;
}

// ---------------- layer-2 aggregation: warp per node, online softmax, H=1 D=64 ----------------
__global__ __launch_bounds__(256) void agg2_kernel(float* __restrict__ out, int Nn)
{
    int warp = (blockIdx.x * blockDim.x + threadIdx.x) >> 5;
    int lane = threadIdx.x & 31;
    if (warp >= Nn) return;
    int n = warp;

    const float2* Q2 = (const float2*)g_Q2;
    const float2* K2 = (const float2*)g_K2;
    const float2* V2 = (const float2*)g_V2;
    const float2* S2 = (const float2*)g_S2;

    float2 q = Q2[(size_t)n * 32 + lane];   // lane holds dims 2*lane..2*lane+1

    int beg = g_rowptr[n];
    int end = g_rowptr[n + 1];

    float m = -1e30f, s = 0.f;
    float2 acc = make_float2(0.f, 0.f);

    if (beg < end) {
        int src = g_psrc[beg];
        float2 kk = K2[(size_t)src * 32 + lane];
        float2 vv = V2[(size_t)src * 32 + lane];
        for (int e = beg; e < end; e++) {
            int nsrc = (e + 1 < end) ? g_psrc[e + 1] : src;
            float2 nk = K2[(size_t)nsrc * 32 + lane];
            float2 nv = V2[(size_t)nsrc * 32 + lane];

            float d = kk.x * q.x + kk.y * q.y;
            #pragma unroll
            for (int off = 16; off > 0; off >>= 1)
                d += __shfl_xor_sync(0xffffffffu, d, off);
            float sc = d * 0.125f;                      // 1/sqrt(64)

            float mn = fmaxf(m, sc);
            float c  = __expf(m - mn);
            float p  = __expf(sc - mn);
            s = s * c + p;
            acc.x = acc.x * c + p * vv.x;
            acc.y = acc.y * c + p * vv.y;
            m = mn;

            kk = nk; vv = nv;
        }
    }

    float inv = 1.f / (s + 1e-16f);
    float2 sk = S2[(size_t)n * 32 + lane];
    float2 o;
    o.x = acc.x * inv + sk.x;
    o.y = acc.y * inv + sk.y;
    ((float2*)out)[(size_t)n * 32 + lane] = o;
}

// ---------------- launch ----------------
extern "C" void kernel_launch(void* const* d_in, const int* in_sizes, int n_in,
                              void* d_out, int out_size)
{
    const float* x   = (const float*)d_in[0];
    const float* Wq1 = (const float*)d_in[1];  const float* bq1 = (const float*)d_in[2];
    const float* Wk1 = (const float*)d_in[3];  const float* bk1 = (const float*)d_in[4];
    const float* Wv1 = (const float*)d_in[5];  const float* bv1 = (const float*)d_in[6];
    const float* Ws1 = (const float*)d_in[7];  const float* bs1 = (const float*)d_in[8];
    const float* Wq2 = (const float*)d_in[9];  const float* bq2 = (const float*)d_in[10];
    const float* Wk2 = (const float*)d_in[11]; const float* bk2 = (const float*)d_in[12];
    const float* Wv2 = (const float*)d_in[13]; const float* bv2 = (const float*)d_in[14];
    const float* Ws2 = (const float*)d_in[15]; const float* bs2 = (const float*)d_in[16];
    const int* esrc  = (const int*)d_in[17];
    const int* edst  = (const int*)d_in[18];
    float* out = (float*)d_out;

    int Nn = in_sizes[0] / 128;
    int E  = in_sizes[17];

    // One-time side-stream + events (created on the correctness call, which
    // precedes graph capture; reused identically on every call -> same work,
    // same output, graph-capturable fork/join).
    static cudaStream_t s2 = nullptr;
    static cudaEvent_t evFork = nullptr, evJoin = nullptr;
    if (s2 == nullptr) {
        cudaStreamCreateWithFlags(&s2, cudaStreamNonBlocking);
        cudaEventCreateWithFlags(&evFork, cudaEventDisableTiming);
        cudaEventCreateWithFlags(&evJoin, cudaEventDisableTiming);
    }

    // ---- fork: CSR build on s2, concurrent with layer-1 projections ----
    cudaEventRecord(evFork, 0);
    cudaStreamWaitEvent(s2, evFork, 0);

    k_zero<<<(Nn + 255) / 256, 256, 0, s2>>>(Nn);
    k_hist<<<(E + 255) / 256, 256, 0, s2>>>(edst, E);
    k_scan<<<1, 1024, 0, s2>>>(Nn);
    k_scatter<<<(E + 255) / 256, 256, 0, s2>>>(esrc, edst, E);
    cudaEventRecord(evJoin, s2);

    // main stream: layer-1 projections (Q,K,V,S via blockIdx.z)
    dim3 g1(2, (Nn + 127) / 128, 4);
    gemm_tc<<<g1, 256>>>(x, Wq1, Wk1, Wv1, Ws1, bq1, bk1, bv1, bs1, Nn, 128, 0);

    // ---- join: agg1 needs both CSR and projections ----
    cudaStreamWaitEvent(0, evJoin, 0);

    int aggBlocks = (Nn + 7) / 8;   // 8 warps per 256-thread block
    agg1_kernel<<<aggBlocks, 256>>>(Nn);

    // layer-2 projections: [N,128] @ [128,64] + b (A = g_h via nullptr)
    dim3 g2(1, (Nn + 127) / 128, 4);
    gemm_tc<<<g2, 256>>>(nullptr, Wq2, Wk2, Wv2, Ws2, bq2, bk2, bv2, bs2, Nn, 64, 4);

    agg2_kernel<<<aggBlocks, 256>>>(out, Nn);
}